// round 17
// baseline (speedup 1.0000x reference)
#include <cuda_runtime.h>
#include <cuda_fp16.h>
#include <math.h>
#include <stdint.h>

#define BB 4
#define SS 4096
#define EE 512
#define HH 8
#define DD 64
#define WW 256
#define BHN (BB*HH)
#define NEG (-1e30f)

// fp16 scratch: projected q/k in [bh][s][d], v transposed [bh][d][s];
// pre-converted inputs Xh and weights Wh.
__device__ __half g_q [(size_t)BHN * SS * DD];
__device__ __half g_k [(size_t)BHN * SS * DD];
__device__ __half g_vt[(size_t)BHN * DD * SS];
__device__ __half g_xq[(size_t)BB * SS * EE];
__device__ __half g_xk[(size_t)BB * SS * EE];
__device__ __half g_xv[(size_t)BB * SS * EE];
__device__ __half g_wq[(size_t)EE * EE];
__device__ __half g_wk[(size_t)EE * EE];
__device__ __half g_wv[(size_t)EE * EE];

__device__ __forceinline__ uint32_t f2h2(float lo, float hi) {
    __half2 h = __floats2half2_rn(lo, hi);
    return *(uint32_t*)&h;
}

// m16n8k16 fp16 mma, fp32 accumulate. A row-major, B col-major.
__device__ __forceinline__ void mma16(float* c,
                                      uint32_t a0, uint32_t a1, uint32_t a2, uint32_t a3,
                                      uint32_t b0, uint32_t b1) {
    asm volatile(
        "mma.sync.aligned.m16n8k16.row.col.f32.f16.f16.f32 "
        "{%0,%1,%2,%3},{%4,%5,%6,%7},{%8,%9},{%0,%1,%2,%3};"
        : "+f"(c[0]), "+f"(c[1]), "+f"(c[2]), "+f"(c[3])
        : "r"(a0), "r"(a1), "r"(a2), "r"(a3), "r"(b0), "r"(b1));
}

// ---------------------------------------------------------------------------
// f32 -> fp16 convert (grid-stride, float4 -> 2x half2).
// ---------------------------------------------------------------------------
__global__ __launch_bounds__(256)
void cvt16(const float4* __restrict__ src, uint32_t* __restrict__ dst, int n4)
{
    int i = blockIdx.x * blockDim.x + threadIdx.x;
    int stride = gridDim.x * blockDim.x;
    for (; i < n4; i += stride) {
        float4 v = src[i];
        dst[2 * i]     = f2h2(v.x, v.y);
        dst[2 * i + 1] = f2h2(v.z, v.w);
    }
}

// ---------------------------------------------------------------------------
// Fused projection GEMMs (fp16 m16n8k16), PURE fp16 staging (inputs and
// weights pre-converted): no CVTs in the hot loop, LDG bytes halved.
// blockIdx.z in {0,1,2} = Q,K,V.  C = (Xh @ Wh^T + bias) * scale.
// Q,K written fp16 [bh][s][d]; V written fp16 transposed [bh][d][s].
// ---------------------------------------------------------------------------
__global__ __launch_bounds__(256, 2)
void proj_mma(const __half* __restrict__ Xq, const __half* __restrict__ Xk,
              const __half* __restrict__ Xv,
              const __half* __restrict__ Wq, const __half* __restrict__ Wk,
              const __half* __restrict__ Wv,
              const float* __restrict__ bq, const float* __restrict__ bk,
              const float* __restrict__ bv,
              __half* __restrict__ Oq, __half* __restrict__ Ok,
              __half* __restrict__ Ovt)
{
    __shared__ uint32_t Ah[8][2][32][4];   // 8KB: A fragments (mt, kstep)
    __shared__ uint32_t Bh[8][2][32][4];   // 8KB: B fragment pairs (np, kstep)

    const int z = blockIdx.z;
    const __half* X   = (z == 0) ? Xq : (z == 1) ? Xk : Xv;
    const __half* Wm  = (z == 0) ? Wq : (z == 1) ? Wk : Wv;
    const float* bias = (z == 0) ? bq : (z == 1) ? bk : bv;
    const float scale = (z == 0) ? 0.125f : 1.0f;

    const int tid = threadIdx.x;
    const int lane = tid & 31;
    const int w = tid >> 5;
    const int wm = w >> 2;
    const int wn = w & 3;
    const int m0 = blockIdx.y * 128;
    const int n0 = blockIdx.x * 128;
    const int g = lane >> 2;
    const int t = lane & 3;

    float acc[4][4][4];
#pragma unroll
    for (int mt = 0; mt < 4; mt++)
#pragma unroll
        for (int nt = 0; nt < 4; nt++)
#pragma unroll
            for (int i = 0; i < 4; i++) acc[mt][nt][i] = 0.f;

    const __half* aB[2];
    const __half* bB[2];
#pragma unroll
    for (int p = 0; p < 2; p++) {
        int idx = w * 2 + p;
        int mt = idx >> 1, sA = idx & 1;
        aB[p] = X + (size_t)(m0 + 16 * mt + g) * EE + 16 * sA + 2 * t;
        int np = idx >> 1, sB = idx & 1;
        bB[p] = Wm + (size_t)(n0 + 16 * np + g) * EE + 16 * sB + 2 * t;
    }

    // Prefetch registers: 4 uint32 (half2) per slot.
    uint32_t pa[2][4], pb[2][4];
#pragma unroll
    for (int p = 0; p < 2; p++) {
        pa[p][0] = *(const uint32_t*)(aB[p]);
        pa[p][1] = *(const uint32_t*)(aB[p] + 8 * EE);
        pa[p][2] = *(const uint32_t*)(aB[p] + 8);
        pa[p][3] = *(const uint32_t*)(aB[p] + 8 * EE + 8);
        pb[p][0] = *(const uint32_t*)(bB[p]);
        pb[p][1] = *(const uint32_t*)(bB[p] + 8);
        pb[p][2] = *(const uint32_t*)(bB[p] + 8 * EE);
        pb[p][3] = *(const uint32_t*)(bB[p] + 8 * EE + 8);
    }

    for (int kc = 0; kc < 16; kc++) {
        // Store prefetched chunk into fragment slots (STS.128, conflict-free).
#pragma unroll
        for (int p = 0; p < 2; p++) {
            int idx = w * 2 + p;
            int f = idx >> 1, s = idx & 1;
            *(uint4*)&Ah[f][s][lane][0] =
                make_uint4(pa[p][0], pa[p][1], pa[p][2], pa[p][3]);
            *(uint4*)&Bh[f][s][lane][0] =
                make_uint4(pb[p][0], pb[p][1], pb[p][2], pb[p][3]);
        }
        __syncthreads();

        // Prefetch chunk kc+1 (LDGs overlap the mma compute below).
        if (kc + 1 < 16) {
            const int koff = (kc + 1) * 32;
#pragma unroll
            for (int p = 0; p < 2; p++) {
                pa[p][0] = *(const uint32_t*)(aB[p] + koff);
                pa[p][1] = *(const uint32_t*)(aB[p] + koff + 8 * EE);
                pa[p][2] = *(const uint32_t*)(aB[p] + koff + 8);
                pa[p][3] = *(const uint32_t*)(aB[p] + koff + 8 * EE + 8);
                pb[p][0] = *(const uint32_t*)(bB[p] + koff);
                pb[p][1] = *(const uint32_t*)(bB[p] + koff + 8);
                pb[p][2] = *(const uint32_t*)(bB[p] + koff + 8 * EE);
                pb[p][3] = *(const uint32_t*)(bB[p] + koff + 8 * EE + 8);
            }
        }

        // Compute: 2 k-steps of 16; 16 mmas per step per warp.
#pragma unroll
        for (int s = 0; s < 2; s++) {
            uint4 bf0 = *(const uint4*)&Bh[wn * 2 + 0][s][lane][0];
            uint4 bf1 = *(const uint4*)&Bh[wn * 2 + 1][s][lane][0];
#pragma unroll
            for (int mt = 0; mt < 4; mt++) {
                uint4 af = *(const uint4*)&Ah[wm * 4 + mt][s][lane][0];
                mma16(acc[mt][0], af.x, af.y, af.z, af.w, bf0.x, bf0.y);
                mma16(acc[mt][1], af.x, af.y, af.z, af.w, bf0.z, bf0.w);
                mma16(acc[mt][2], af.x, af.y, af.z, af.w, bf1.x, bf1.y);
                mma16(acc[mt][3], af.x, af.y, af.z, af.w, bf1.z, bf1.w);
            }
        }
        __syncthreads();
    }

    // Epilogue: bias + scale, convert fp16, permuted store.
#pragma unroll
    for (int mt = 0; mt < 4; mt++) {
        int r0 = m0 + wm * 64 + mt * 16 + g;
        int r1 = r0 + 8;
        int b0i = r0 >> 12, s0i = r0 & (SS - 1);
        int b1i = r1 >> 12, s1i = r1 & (SS - 1);
#pragma unroll
        for (int nt = 0; nt < 4; nt++) {
            int n = n0 + wn * 32 + nt * 8 + 2 * t;
            int h = n >> 6, d = n & 63;
            float2 bi = *(const float2*)(bias + n);
            float v00 = (acc[mt][nt][0] + bi.x) * scale;
            float v01 = (acc[mt][nt][1] + bi.y) * scale;
            float v10 = (acc[mt][nt][2] + bi.x) * scale;
            float v11 = (acc[mt][nt][3] + bi.y) * scale;
            if (z != 2) {
                __half* Out = (z == 0) ? Oq : Ok;
                *(uint32_t*)&Out[((size_t)(b0i * HH + h) * SS + s0i) * DD + d] =
                    f2h2(v00, v01);
                *(uint32_t*)&Out[((size_t)(b1i * HH + h) * SS + s1i) * DD + d] =
                    f2h2(v10, v11);
            } else {
                size_t c0 = ((size_t)((b0i * HH + h) * 64 + d)) * SS;
                size_t c1 = ((size_t)((b1i * HH + h) * 64 + d)) * SS;
                Ovt[c0 + s0i]      = __float2half_rn(v00);
                Ovt[c0 + SS + s0i] = __float2half_rn(v01);
                Ovt[c1 + s1i]      = __float2half_rn(v10);
                Ovt[c1 + SS + s1i] = __float2half_rn(v11);
            }
        }
    }
}

// ---------------------------------------------------------------------------
// Band attention (fp16 m16n8k16) — R16 verbatim (96.7us, known good).
// ---------------------------------------------------------------------------
#define QIDX(s, mq, ln) ((((s) * 8 + (mq)) * 32 + (ln)) * 4)
#define KIDX(s, np, ln) ((((s) * 4 + (np)) * 32 + (ln)) * 4)
#define SMEM_ATTN (48 * 1024)

__global__ __launch_bounds__(128)
void attn_mma(float* __restrict__ out)
{
    extern __shared__ uint32_t dsm[];
    uint32_t* Qf  = dsm;                 // 16KB
    uint32_t* Kf0 = dsm + 4096;          // 8KB
    uint32_t* Vf0 = dsm + 6144;          // 8KB
    uint32_t* Kf1 = dsm + 8192;          // 8KB
    uint32_t* Vf1 = dsm + 10240;         // 8KB

    const int bh = blockIdx.y;
    const int bb = bh >> 3;
    const int hh = bh & 7;
    const int i0 = blockIdx.x * 128;
    const int tid = threadIdx.x;
    const int w = tid >> 5;
    const int lane = tid & 31;
    const int g = lane >> 2;
    const int t = lane & 3;

    const __half* qg = g_q  + (size_t)bh * SS * DD;
    const __half* kg = g_k  + (size_t)bh * SS * DD;
    const __half* vt = g_vt + (size_t)bh * DD * SS;

    auto stage = [&](int cg, uint32_t* Kb, uint32_t* Vb) {
        const int j0 = i0 - WW + cg * 64;
        const __half* kp = kg + (size_t)j0 * DD;
        const __half* vp = vt + j0;
#pragma unroll
        for (int p = 0; p < 4; p++) {
            int idx = w * 4 + p;
            int np = idx >> 2, s = idx & 3;
            int n = 16 * np + g;
            int c0 = 16 * s + 2 * t;
            uint4 u;
            u.x = *(const uint32_t*)(kp + (size_t)n * DD + c0);
            u.y = *(const uint32_t*)(kp + (size_t)n * DD + c0 + 8);
            u.z = *(const uint32_t*)(kp + (size_t)(n + 8) * DD + c0);
            u.w = *(const uint32_t*)(kp + (size_t)(n + 8) * DD + c0 + 8);
            *(uint4*)&Kb[KIDX(s, np, lane)] = u;
        }
#pragma unroll
        for (int p = 0; p < 4; p++) {
            int idx = w * 4 + p;
            int np = idx >> 2, s = idx & 3;
            int n = 16 * np + g;
            int c0 = 16 * s + 2 * t;
            uint4 u;
            u.x = *(const uint32_t*)(vp + (size_t)n * SS + c0);
            u.y = *(const uint32_t*)(vp + (size_t)n * SS + c0 + 8);
            u.z = *(const uint32_t*)(vp + (size_t)(n + 8) * SS + c0);
            u.w = *(const uint32_t*)(vp + (size_t)(n + 8) * SS + c0 + 8);
            *(uint4*)&Vb[KIDX(s, np, lane)] = u;
        }
    };

#pragma unroll
    for (int p = 0; p < 8; p++) {
        int idx = w * 8 + p;
        int mq = idx >> 2, s = idx & 3;
        const __half* r0 = qg + (size_t)(i0 + 16 * mq + g) * DD + 16 * s + 2 * t;
        uint4 u;
        u.x = *(const uint32_t*)(r0);
        u.y = *(const uint32_t*)(r0 + 8 * DD);
        u.z = *(const uint32_t*)(r0 + 8);
        u.w = *(const uint32_t*)(r0 + 8 * DD + 8);
        *(uint4*)&Qf[QIDX(s, mq, lane)] = u;
    }

    float oacc[2][8][4];
#pragma unroll
    for (int mt = 0; mt < 2; mt++)
#pragma unroll
        for (int nt = 0; nt < 8; nt++)
#pragma unroll
            for (int i = 0; i < 4; i++) oacc[mt][nt][i] = 0.f;
    float lpA[2] = {0.f, 0.f}, lpB[2] = {0.f, 0.f};

    const int cgLo = (i0 < WW) ? (WW - i0) / 64 : 0;
    const int cgHiRaw = (SS - 64 - i0 + WW) / 64;
    const int cgHi = cgHiRaw < 9 ? cgHiRaw : 9;

    stage(cgLo, Kf0, Vf0);
    __syncthreads();

    for (int cg = cgLo; cg <= cgHi; cg++) {
        const int b = (cg - cgLo) & 1;
        uint32_t* Kb = b ? Kf1 : Kf0;
        uint32_t* Vb = b ? Vf1 : Vf0;

        if (cg < cgHi) stage(cg + 1, b ? Kf0 : Kf1, b ? Vf0 : Vf1);

        float sc[2][8][4];
#pragma unroll
        for (int mt = 0; mt < 2; mt++)
#pragma unroll
            for (int nt = 0; nt < 8; nt++)
#pragma unroll
                for (int i = 0; i < 4; i++) sc[mt][nt][i] = 0.f;
#pragma unroll
        for (int s = 0; s < 4; s++) {
            uint4 q0 = *(const uint4*)&Qf[QIDX(s, 2 * w + 0, lane)];
            uint4 q1 = *(const uint4*)&Qf[QIDX(s, 2 * w + 1, lane)];
#pragma unroll
            for (int np = 0; np < 4; np++) {
                uint4 u = *(const uint4*)&Kb[KIDX(s, np, lane)];
                mma16(sc[0][2 * np],     q0.x, q0.y, q0.z, q0.w, u.x, u.y);
                mma16(sc[0][2 * np + 1], q0.x, q0.y, q0.z, q0.w, u.z, u.w);
                mma16(sc[1][2 * np],     q1.x, q1.y, q1.z, q1.w, u.x, u.y);
                mma16(sc[1][2 * np + 1], q1.x, q1.y, q1.z, q1.w, u.z, u.w);
            }
        }

        if (cg <= 1) {
#pragma unroll
            for (int mt = 0; mt < 2; mt++) {
                int lo = 32 * w + 16 * mt + g - 64 * cg;
#pragma unroll
                for (int nt = 0; nt < 8; nt++) {
                    int c0 = 8 * nt + 2 * t;
                    if (c0     < lo)     sc[mt][nt][0] = NEG;
                    if (c0 + 1 < lo)     sc[mt][nt][1] = NEG;
                    if (c0     < lo + 8) sc[mt][nt][2] = NEG;
                    if (c0 + 1 < lo + 8) sc[mt][nt][3] = NEG;
                }
            }
        } else if (cg >= 8) {
#pragma unroll
            for (int mt = 0; mt < 2; mt++) {
                int hi = 32 * w + 16 * mt + g + 512 - 64 * cg;
#pragma unroll
                for (int nt = 0; nt < 8; nt++) {
                    int c0 = 8 * nt + 2 * t;
                    if (c0     > hi)     sc[mt][nt][0] = NEG;
                    if (c0 + 1 > hi)     sc[mt][nt][1] = NEG;
                    if (c0     > hi + 8) sc[mt][nt][2] = NEG;
                    if (c0 + 1 > hi + 8) sc[mt][nt][3] = NEG;
                }
            }
        }

#pragma unroll
        for (int mt = 0; mt < 2; mt++) {
#pragma unroll
            for (int nt = 0; nt < 8; nt++) {
                sc[mt][nt][0] = __expf(sc[mt][nt][0]);
                sc[mt][nt][1] = __expf(sc[mt][nt][1]);
                sc[mt][nt][2] = __expf(sc[mt][nt][2]);
                sc[mt][nt][3] = __expf(sc[mt][nt][3]);
                lpA[mt] += sc[mt][nt][0] + sc[mt][nt][1];
                lpB[mt] += sc[mt][nt][2] + sc[mt][nt][3];
            }
        }

#pragma unroll
        for (int s = 0; s < 4; s++) {
            uint32_t a[2][4];
#pragma unroll
            for (int mt = 0; mt < 2; mt++) {
                a[mt][0] = f2h2(sc[mt][2 * s][0],     sc[mt][2 * s][1]);
                a[mt][1] = f2h2(sc[mt][2 * s][2],     sc[mt][2 * s][3]);
                a[mt][2] = f2h2(sc[mt][2 * s + 1][0], sc[mt][2 * s + 1][1]);
                a[mt][3] = f2h2(sc[mt][2 * s + 1][2], sc[mt][2 * s + 1][3]);
            }
#pragma unroll
            for (int np = 0; np < 4; np++) {
                uint4 u = *(const uint4*)&Vb[KIDX(s, np, lane)];
                mma16(oacc[0][2 * np],     a[0][0], a[0][1], a[0][2], a[0][3], u.x, u.y);
                mma16(oacc[0][2 * np + 1], a[0][0], a[0][1], a[0][2], a[0][3], u.z, u.w);
                mma16(oacc[1][2 * np],     a[1][0], a[1][1], a[1][2], a[1][3], u.x, u.y);
                mma16(oacc[1][2 * np + 1], a[1][0], a[1][1], a[1][2], a[1][3], u.z, u.w);
            }
        }

        __syncthreads();
    }

#pragma unroll
    for (int mt = 0; mt < 2; mt++) {
        float sA = lpA[mt], sB = lpB[mt];
        sA += __shfl_xor_sync(0xffffffffu, sA, 1);
        sA += __shfl_xor_sync(0xffffffffu, sA, 2);
        sB += __shfl_xor_sync(0xffffffffu, sB, 1);
        sB += __shfl_xor_sync(0xffffffffu, sB, 2);
        float iA = 1.f / sA, iB = 1.f / sB;
        size_t baseA = (size_t)(i0 + 32 * w + 16 * mt + g) * 2048
                     + (size_t)(bb * 512 + hh * 64);
        size_t baseB = baseA + (size_t)8 * 2048;
#pragma unroll
        for (int nt = 0; nt < 8; nt++) {
            int d = 8 * nt + 2 * t;
            float2 o;
            o.x = oacc[mt][nt][0] * iA; o.y = oacc[mt][nt][1] * iA;
            *(float2*)(out + baseA + d) = o;
            o.x = oacc[mt][nt][2] * iB; o.y = oacc[mt][nt][3] * iB;
            *(float2*)(out + baseB + d) = o;
        }
    }
}

// ---------------------------------------------------------------------------
extern "C" void kernel_launch(void* const* d_in, const int* in_sizes, int n_in,
                              void* d_out, int out_size)
{
    (void)in_sizes; (void)n_in; (void)out_size;
    const float* query = (const float*)d_in[0];
    const float* key   = (const float*)d_in[1];
    const float* value = (const float*)d_in[2];
    const float* Wq = (const float*)d_in[4];
    const float* bq = (const float*)d_in[5];
    const float* Wk = (const float*)d_in[6];
    const float* bk = (const float*)d_in[7];
    const float* Wv = (const float*)d_in[8];
    const float* bv = (const float*)d_in[9];
    float* out = (float*)d_out;

    __half *qp, *kp, *vtp, *xq, *xk, *xv, *wq, *wk, *wv;
    cudaGetSymbolAddress((void**)&qp,  g_q);
    cudaGetSymbolAddress((void**)&kp,  g_k);
    cudaGetSymbolAddress((void**)&vtp, g_vt);
    cudaGetSymbolAddress((void**)&xq,  g_xq);
    cudaGetSymbolAddress((void**)&xk,  g_xk);
    cudaGetSymbolAddress((void**)&xv,  g_xv);
    cudaGetSymbolAddress((void**)&wq,  g_wq);
    cudaGetSymbolAddress((void**)&wk,  g_wk);
    cudaGetSymbolAddress((void**)&wv,  g_wv);

    static int smem_set = 0;
    if (!smem_set) {
        cudaFuncSetAttribute(attn_mma,
                             cudaFuncAttributeMaxDynamicSharedMemorySize,
                             SMEM_ATTN);
        smem_set = 1;
    }

    // Pre-convert inputs and weights to fp16 (grid-stride, graph-safe).
    const int nX4 = BB * SS * EE / 4;     // 2,097,152
    const int nW4 = EE * EE / 4;          // 65,536
    cvt16<<<2048, 256>>>((const float4*)query, (uint32_t*)xq, nX4);
    cvt16<<<2048, 256>>>((const float4*)key,   (uint32_t*)xk, nX4);
    cvt16<<<2048, 256>>>((const float4*)value, (uint32_t*)xv, nX4);
    cvt16<<<256,  256>>>((const float4*)Wq,    (uint32_t*)wq, nW4);
    cvt16<<<256,  256>>>((const float4*)Wk,    (uint32_t*)wk, nW4);
    cvt16<<<256,  256>>>((const float4*)Wv,    (uint32_t*)wv, nW4);

    dim3 gp(EE / 128, (BB * SS) / 128, 3);   // fused Q/K/V projections
    proj_mma<<<gp, 256>>>(xq, xk, xv, wq, wk, wv, bq, bk, bv, qp, kp, vtp);

    attn_mma<<<dim3(SS / 128, BHN), 128, SMEM_ATTN>>>(out);
}